// round 16
// baseline (speedup 1.0000x reference)
#include <cuda_runtime.h>
#include <cuda_bf16.h>
#include <cstdint>

#define TPB 256
#define WPB (TPB / 32)      // warps per block = 8
#define GPW 128             // gaussians per warp (4 per lane)
#define GPB (WPB * GPW)     // gaussians per block = 1024

__device__ __forceinline__ void cov_from_q(float4 qv, float s0, float s1, float s2,
                                           float* __restrict__ o /* 9 floats */)
{
    float r = qv.x, x = qv.y, y = qv.z, z = qv.w;
    float n2  = r*r + x*x + y*y + z*z;
    float inv = rsqrtf(fmaxf(n2, 1e-24f));   // == 1/max(||q||,1e-12)
    r *= inv; x *= inv; y *= inv; z *= inv;

    float R00 = 1.0f - 2.0f*(y*y + z*z);
    float R01 = 2.0f*(x*y - r*z);
    float R02 = 2.0f*(x*z + r*y);
    float R10 = 2.0f*(x*y + r*z);
    float R11 = 1.0f - 2.0f*(x*x + z*z);
    float R12 = 2.0f*(y*z - r*x);
    float R20 = 2.0f*(x*z - r*y);
    float R21 = 2.0f*(y*z + r*x);
    float R22 = 1.0f - 2.0f*(x*x + y*y);

    float t0 = s0*s0, t1 = s1*s1, t2 = s2*s2;

    float c01 = R00*R10*t0 + R01*R11*t1 + R02*R12*t2;
    float c02 = R00*R20*t0 + R01*R21*t1 + R02*R22*t2;
    float c12 = R10*R20*t0 + R11*R21*t1 + R12*R22*t2;
    o[0] = R00*R00*t0 + R01*R01*t1 + R02*R02*t2;
    o[1] = c01;
    o[2] = c02;
    o[3] = c01;
    o[4] = R10*R10*t0 + R11*R11*t1 + R12*R12*t2;
    o[5] = c12;
    o[6] = c02;
    o[7] = c12;
    o[8] = R20*R20*t0 + R21*R21*t1 + R22*R22*t2;
}

__global__ __launch_bounds__(TPB, 5) void gaussians_cov_kernel(
    const float4* __restrict__ quat,   // [n] as float4 (r,x,y,z)
    const float*  __restrict__ scales, // [n*3]
    float*        __restrict__ out,    // [n*9]
    int n)
{
    // warp-private output staging (36 KB)
    __shared__ float so[WPB * 9 * GPW];

    const int wid      = threadIdx.x >> 5;
    const int lane     = threadIdx.x & 31;
    const int warpBase = blockIdx.x * GPB + wid * GPW;

    float* wso = so + wid * (9 * GPW);

    if (warpBase + GPW <= n) {
        // ---- front-batch ALL global loads (16 per lane in flight) ----
        float4 q[4];
        #pragma unroll
        for (int j = 0; j < 4; j++)
            q[j] = __ldg(&quat[warpBase + j * 32 + lane]);     // LDG.128 x4

        float sv[12];
        const float* sp = scales + (size_t)warpBase * 3;
        #pragma unroll
        for (int j = 0; j < 4; j++) {
            int t3 = (j * 32 + lane) * 3;
            sv[j*3+0] = __ldg(&sp[t3 + 0]);                    // LDG.32 x12
            sv[j*3+1] = __ldg(&sp[t3 + 1]);
            sv[j*3+2] = __ldg(&sp[t3 + 2]);
        }

        // compute 4 covariances; stride-9 STS is conflict-free (gcd(9,32)=1)
        #pragma unroll
        for (int j = 0; j < 4; j++) {
            int t = j * 32 + lane;
            cov_from_q(q[j], sv[j*3+0], sv[j*3+1], sv[j*3+2], &wso[t * 9]);
        }
        __syncwarp();

        // ---- coalesced write-through writeback: 9 float4 per lane ----
        float4*       o4 = reinterpret_cast<float4*>(out + (size_t)warpBase * 9);
        const float4* s4 = reinterpret_cast<const float4*>(wso);
        #pragma unroll
        for (int k = 0; k < 9; k++)
            __stwt(&o4[k * 32 + lane], s4[k * 32 + lane]);
    } else {
        // ---- tail: guarded scalar path ----
        for (int g = warpBase + lane; g < n; g += 32) {
            float4 qv = quat[g];
            float  oo[9];
            cov_from_q(qv, scales[(size_t)g*3+0], scales[(size_t)g*3+1],
                           scales[(size_t)g*3+2], oo);
            #pragma unroll
            for (int k = 0; k < 9; k++)
                __stwt(&out[(size_t)g * 9 + k], oo[k]);
        }
    }
}

extern "C" void kernel_launch(void* const* d_in, const int* in_sizes, int n_in,
                              void* d_out, int out_size) {
    const float4* quat   = (const float4*)d_in[0];   // quaternions [n,4]
    const float*  scales = (const float*)d_in[1];    // scales [n,3]
    float*        out    = (float*)d_out;            // covariance [n,3,3]
    int n = in_sizes[0] / 4;

    int blocks = (n + GPB - 1) / GPB;
    gaussians_cov_kernel<<<blocks, TPB>>>(quat, scales, out, n);
}